// round 1
// baseline (speedup 1.0000x reference)
#include <cuda_runtime.h>
#include <cuda_bf16.h>
#include <cstddef>

// Problem constants (from reference)
#define BATCH   8192
#define BOX     10
#define PAIR    90      // BOX*(BOX-1)
#define NUM_QT  65
#define NUM_OT  151
#define TOTAL_UPDATES (BATCH * PAIR)   // 737280

__global__ void scatter_add_kernel(const int* __restrict__ obj_label,
                                   const int* __restrict__ qus_type,
                                   const float* __restrict__ attention,
                                   float* __restrict__ out) {
    int idx = blockIdx.x * blockDim.x + threadIdx.x;
    if (idx >= TOTAL_UPDATES) return;

    int b  = idx / PAIR;
    int p  = idx - b * PAIR;          // pair index 0..89
    int i  = p / (BOX - 1);           // 0..9
    int jj = p - i * (BOX - 1);       // 0..8
    int j  = jj + (jj >= i);          // skip the diagonal

    int   qt  = qus_type[b];
    int   oli = obj_label[b * BOX + i];   // ol2
    int   olj = obj_label[b * BOX + j];   // ol1
    float a   = attention[b * BOX + i] * attention[b * BOX + j];

    size_t off = ((((size_t)qt * PAIR + p) * NUM_OT) + olj) * NUM_OT + oli;
    atomicAdd(out + off, a);
}

extern "C" void kernel_launch(void* const* d_in, const int* in_sizes, int n_in,
                              void* d_out, int out_size) {
    const int*   obj_label    = (const int*)d_in[0];
    const int*   qus_type     = (const int*)d_in[1];
    const float* attention    = (const float*)d_in[2];
    const float* score_matrix = (const float*)d_in[3];
    float*       out          = (float*)d_out;

    // 1) Bulk copy score_matrix -> out (533 MB, HBM-bound; this is the roofline)
    cudaMemcpyAsync(out, score_matrix, (size_t)out_size * sizeof(float),
                    cudaMemcpyDeviceToDevice);

    // 2) Scatter-add the 737K attention products (ordered behind the copy on
    //    the same stream; negligible cost vs the copy)
    int threads = 256;
    int blocks  = (TOTAL_UPDATES + threads - 1) / threads;
    scatter_add_kernel<<<blocks, threads>>>(obj_label, qus_type, attention, out);
}

// round 2
// speedup vs baseline: 1.8205x; 1.8205x over previous
#include <cuda_runtime.h>
#include <cuda_bf16.h>
#include <cstddef>

// Problem constants (from reference)
#define BATCH   8192
#define BOX     10
#define PAIR    90      // BOX*(BOX-1)
#define NUM_QT  65
#define NUM_OT  151
#define TOTAL_UPDATES (BATCH * PAIR)           // 737280
#define TOTAL_ELEMS   133385850LL              // 65*90*151*151
#define VEC_ELEMS     (TOTAL_ELEMS / 4)        // 33346462 float4
#define TAIL_START    (VEC_ELEMS * 4)          // 2 scalar tail elems

// SM-driven bulk copy: float4 grid-stride. This is the HBM roofline.
__global__ void copy_kernel(const float4* __restrict__ src,
                            float4* __restrict__ dst,
                            const float* __restrict__ src_s,
                            float* __restrict__ dst_s) {
    long long stride = (long long)gridDim.x * blockDim.x;
    for (long long i = (long long)blockIdx.x * blockDim.x + threadIdx.x;
         i < VEC_ELEMS; i += stride) {
        dst[i] = src[i];
    }
    // tail (2 elements)
    long long t = (long long)blockIdx.x * blockDim.x + threadIdx.x;
    if (t < (TOTAL_ELEMS - TAIL_START)) {
        dst_s[TAIL_START + t] = src_s[TAIL_START + t];
    }
}

__global__ void scatter_add_kernel(const int* __restrict__ obj_label,
                                   const int* __restrict__ qus_type,
                                   const float* __restrict__ attention,
                                   float* __restrict__ out) {
    int idx = blockIdx.x * blockDim.x + threadIdx.x;
    if (idx >= TOTAL_UPDATES) return;

    int b  = idx / PAIR;
    int p  = idx - b * PAIR;          // pair index 0..89
    int i  = p / (BOX - 1);           // 0..9
    int jj = p - i * (BOX - 1);       // 0..8
    int j  = jj + (jj >= i);          // skip the diagonal

    int   qt  = __ldg(qus_type + b);
    int   oli = __ldg(obj_label + b * BOX + i);   // ol2
    int   olj = __ldg(obj_label + b * BOX + j);   // ol1
    float a   = __ldg(attention + b * BOX + i) * __ldg(attention + b * BOX + j);

    size_t off = ((((size_t)qt * PAIR + p) * NUM_OT) + olj) * NUM_OT + oli;
    atomicAdd(out + off, a);
}

extern "C" void kernel_launch(void* const* d_in, const int* in_sizes, int n_in,
                              void* d_out, int out_size) {
    const int*   obj_label    = (const int*)d_in[0];
    const int*   qus_type     = (const int*)d_in[1];
    const float* attention    = (const float*)d_in[2];
    const float* score_matrix = (const float*)d_in[3];
    float*       out          = (float*)d_out;

    // 1) SM-driven bulk copy (533 MB read + 533 MB write, HBM-bound)
    {
        int threads = 256;
        int blocks  = 148 * 8;   // plenty of waves for full-chip DRAM saturation
        copy_kernel<<<blocks, threads>>>((const float4*)score_matrix,
                                         (float4*)out,
                                         score_matrix, out);
    }

    // 2) Scatter-add the 737K attention products (ordered behind the copy)
    {
        int threads = 256;
        int blocks  = (TOTAL_UPDATES + threads - 1) / threads;
        scatter_add_kernel<<<blocks, threads>>>(obj_label, qus_type, attention, out);
    }
}

// round 3
// speedup vs baseline: 1.8504x; 1.0164x over previous
#include <cuda_runtime.h>
#include <cuda_bf16.h>
#include <cstddef>

// Problem constants (from reference)
#define BATCH   8192
#define BOX     10
#define PAIR    90                    // BOX*(BOX-1)
#define NUM_QT  65
#define NUM_OT  151
#define PLANE   (NUM_OT * NUM_OT)     // 22801 floats per (qt,pair) plane
#define NPLANES (NUM_QT * PAIR)       // 5850

// Scratch: batch indices bucketed by question type
__device__ int g_qt_off[NUM_QT + 1];
__device__ int g_qt_list[BATCH];

// ---------------------------------------------------------------------------
// Kernel 1: bucket the 8192 batches by qus_type (single CTA, ~2-3us)
// ---------------------------------------------------------------------------
__global__ void bucket_kernel(const int* __restrict__ qus_type) {
    __shared__ int cnt[NUM_QT];
    __shared__ int cursor[NUM_QT];
    int tid = threadIdx.x;

    if (tid < NUM_QT) cnt[tid] = 0;
    __syncthreads();

    for (int b = tid; b < BATCH; b += blockDim.x)
        atomicAdd(&cnt[qus_type[b]], 1);
    __syncthreads();

    if (tid == 0) {
        int run = 0;
        for (int q = 0; q < NUM_QT; q++) {
            g_qt_off[q] = run;
            cursor[q]   = run;
            run += cnt[q];
        }
        g_qt_off[NUM_QT] = run;   // == BATCH
    }
    __syncthreads();

    for (int b = tid; b < BATCH; b += blockDim.x) {
        int pos = atomicAdd(&cursor[qus_type[b]], 1);
        g_qt_list[pos] = b;
    }
}

// ---------------------------------------------------------------------------
// Kernel 2: one CTA per (qt, pair) plane.
//   Phase A: copy the 22801-float plane src->dst (float4 body, scalar head/tail)
//   Phase B: apply this plane's ~126 scatter-adds (atomics hit L2-hot lines)
// ---------------------------------------------------------------------------
__global__ __launch_bounds__(512) void fused_plane_kernel(
        const float* __restrict__ src,
        float*       __restrict__ dst,
        const int*   __restrict__ obj_label,
        const float* __restrict__ attention) {
    int plane = blockIdx.x;                 // 0 .. 5849
    int qt = plane / PAIR;
    int p  = plane - qt * PAIR;             // pair index 0..89
    size_t base = (size_t)plane * PLANE;

    const float* s = src + base;
    float*       d = dst + base;
    int tid = threadIdx.x;

    // --- Phase A: copy ---
    int head = (int)((4 - (base & 3)) & 3);         // scalars to reach 16B align
    if (tid < head) d[tid] = __ldcs(s + tid);

    int nvec = (PLANE - head) >> 2;                 // float4 body count
    const float4* s4 = (const float4*)(s + head);
    float4*       d4 = (float4*)(d + head);
    #pragma unroll 4
    for (int i = tid; i < nvec; i += blockDim.x)
        d4[i] = __ldcs(s4 + i);

    int tail_start = head + (nvec << 2);
    int ntail = PLANE - tail_start;                 // 0..3 scalars
    if (tid < ntail) d[tail_start + tid] = __ldcs(s + tail_start + tid);

    __syncthreads();   // plane fully written before this CTA's atomics

    // --- Phase B: scatter-adds for this plane ---
    int i  = p / (BOX - 1);
    int jj = p - i * (BOX - 1);
    int j  = jj + (jj >= i);

    int start = g_qt_off[qt];
    int end   = g_qt_off[qt + 1];
    for (int u = start + tid; u < end; u += blockDim.x) {
        int b   = g_qt_list[u];
        int ol1 = __ldg(obj_label + b * BOX + j);
        int ol2 = __ldg(obj_label + b * BOX + i);
        float a = __ldg(attention + b * BOX + i) * __ldg(attention + b * BOX + j);
        atomicAdd(d + ol1 * NUM_OT + ol2, a);
    }
}

extern "C" void kernel_launch(void* const* d_in, const int* in_sizes, int n_in,
                              void* d_out, int out_size) {
    const int*   obj_label    = (const int*)d_in[0];
    const int*   qus_type     = (const int*)d_in[1];
    const float* attention    = (const float*)d_in[2];
    const float* score_matrix = (const float*)d_in[3];
    float*       out          = (float*)d_out;

    bucket_kernel<<<1, 1024>>>(qus_type);
    fused_plane_kernel<<<NPLANES, 512>>>(score_matrix, out, obj_label, attention);
}

// round 4
// speedup vs baseline: 2.0443x; 1.1048x over previous
#include <cuda_runtime.h>
#include <cuda_bf16.h>
#include <cstddef>

// Problem constants (from reference)
#define BATCH   8192
#define BOX     10
#define PAIR    90                    // BOX*(BOX-1)
#define NUM_QT  65
#define NUM_OT  151
#define PLANE   (NUM_OT * NUM_OT)     // 22801 floats per (qt,pair) plane
#define NPLANES (NUM_QT * PAIR)       // 5850
#define NTHREADS 512

// Scratch: batch indices bucketed by question type
__device__ int g_qt_off[NUM_QT + 1];
__device__ int g_qt_list[BATCH];

// ---------------------------------------------------------------------------
// Kernel 1: bucket the 8192 batches by qus_type (single CTA, ~2-3us)
// ---------------------------------------------------------------------------
__global__ void bucket_kernel(const int* __restrict__ qus_type) {
    __shared__ int cnt[NUM_QT];
    __shared__ int cursor[NUM_QT];
    int tid = threadIdx.x;

    if (tid < NUM_QT) cnt[tid] = 0;
    __syncthreads();

    for (int b = tid; b < BATCH; b += blockDim.x)
        atomicAdd(&cnt[qus_type[b]], 1);
    __syncthreads();

    if (tid == 0) {
        int run = 0;
        for (int q = 0; q < NUM_QT; q++) {
            g_qt_off[q] = run;
            cursor[q]   = run;
            run += cnt[q];
        }
        g_qt_off[NUM_QT] = run;   // == BATCH
    }
    __syncthreads();

    for (int b = tid; b < BATCH; b += blockDim.x) {
        int pos = atomicAdd(&cursor[qus_type[b]], 1);
        g_qt_list[pos] = b;
    }
}

// ---------------------------------------------------------------------------
// Kernel 2: one CTA per (qt, pair) plane.
//   Phase A: copy the plane with register-blocked float4 (4 batched LDGs,
//            then 4 STGs -> MLP=4 per thread, streaming hints both ways)
//   Phase B: apply this plane's ~126 scatter-adds (atomics hit L2-hot lines)
// ---------------------------------------------------------------------------
__global__ __launch_bounds__(NTHREADS) void fused_plane_kernel(
        const float* __restrict__ src,
        float*       __restrict__ dst,
        const int*   __restrict__ obj_label,
        const float* __restrict__ attention) {
    int plane = blockIdx.x;                 // 0 .. 5849
    int qt = plane / PAIR;
    int p  = plane - qt * PAIR;             // pair index 0..89
    size_t base = (size_t)plane * PLANE;

    const float* s = src + base;
    float*       d = dst + base;
    int tid = threadIdx.x;

    // --- Phase A: copy ---
    int head = (int)((4 - (base & 3)) & 3);         // scalars to reach 16B align
    if (tid < head) __stcs(d + tid, __ldcs(s + tid));

    int nvec = (PLANE - head) >> 2;                 // float4 body count (~5699)
    const float4* s4 = (const float4*)(s + head);
    float4*       d4 = (float4*)(d + head);

    // Register-blocked: 4 independent loads in flight, then 4 stores.
    for (int i0 = tid; i0 < nvec; i0 += 4 * NTHREADS) {
        int i1 = i0 + NTHREADS;
        int i2 = i0 + 2 * NTHREADS;
        int i3 = i0 + 3 * NTHREADS;
        float4 r0, r1, r2, r3;
        bool v1 = i1 < nvec, v2 = i2 < nvec, v3 = i3 < nvec;
        r0 = __ldcs(s4 + i0);
        if (v1) r1 = __ldcs(s4 + i1);
        if (v2) r2 = __ldcs(s4 + i2);
        if (v3) r3 = __ldcs(s4 + i3);
        __stcs(d4 + i0, r0);
        if (v1) __stcs(d4 + i1, r1);
        if (v2) __stcs(d4 + i2, r2);
        if (v3) __stcs(d4 + i3, r3);
    }

    int tail_start = head + (nvec << 2);
    int ntail = PLANE - tail_start;                 // 0..3 scalars
    if (tid < ntail) __stcs(d + tail_start + tid, __ldcs(s + tail_start + tid));

    __syncthreads();   // plane fully written before this CTA's atomics

    // --- Phase B: scatter-adds for this plane ---
    int i  = p / (BOX - 1);
    int jj = p - i * (BOX - 1);
    int j  = jj + (jj >= i);

    int start = g_qt_off[qt];
    int end   = g_qt_off[qt + 1];
    for (int u = start + tid; u < end; u += blockDim.x) {
        int b   = g_qt_list[u];
        int ol1 = __ldg(obj_label + b * BOX + j);
        int ol2 = __ldg(obj_label + b * BOX + i);
        float a = __ldg(attention + b * BOX + i) * __ldg(attention + b * BOX + j);
        atomicAdd(d + ol1 * NUM_OT + ol2, a);
    }
}

extern "C" void kernel_launch(void* const* d_in, const int* in_sizes, int n_in,
                              void* d_out, int out_size) {
    const int*   obj_label    = (const int*)d_in[0];
    const int*   qus_type     = (const int*)d_in[1];
    const float* attention    = (const float*)d_in[2];
    const float* score_matrix = (const float*)d_in[3];
    float*       out          = (float*)d_out;

    bucket_kernel<<<1, 1024>>>(qus_type);
    fused_plane_kernel<<<NPLANES, NTHREADS>>>(score_matrix, out, obj_label, attention);
}

// round 5
// speedup vs baseline: 2.1180x; 1.0360x over previous
#include <cuda_runtime.h>
#include <cuda_bf16.h>
#include <cstddef>

// Problem constants (from reference)
#define BATCH   8192
#define BOX     10
#define PAIR    90                    // BOX*(BOX-1)
#define NUM_QT  65
#define NUM_OT  151
#define PLANE   (NUM_OT * NUM_OT)     // 22801 floats per (qt,pair) plane
#define NPLANES (NUM_QT * PAIR)       // 5850
#define NTHREADS 512
#define QT_PER_THREAD (BATCH / NTHREADS)   // 16 exactly

// ---------------------------------------------------------------------------
// Single fused kernel: one CTA per (qt, pair) plane.
//   Phase A: copy the 22801-float plane (register-blocked float4, streaming)
//            + prefetch this thread's 16 qus_type values into registers
//   Phase B: predicated scan over all 8192 batches; atomicAdd the ~126
//            matching attention products into the just-copied (L2-hot) plane
// ---------------------------------------------------------------------------
__global__ __launch_bounds__(NTHREADS) void fused_plane_kernel(
        const float* __restrict__ src,
        float*       __restrict__ dst,
        const int*   __restrict__ obj_label,
        const int*   __restrict__ qus_type,
        const float* __restrict__ attention) {
    int plane = blockIdx.x;                 // 0 .. 5849
    int qt = plane / PAIR;
    int p  = plane - qt * PAIR;             // pair index 0..89
    size_t base = (size_t)plane * PLANE;

    const float* s = src + base;
    float*       d = dst + base;
    int tid = threadIdx.x;

    // --- Phase A: copy ---
    int head = (int)((4 - (base & 3)) & 3);         // scalars to reach 16B align
    if (tid < head) __stcs(d + tid, __ldcs(s + tid));

    int nvec = (PLANE - head) >> 2;                 // float4 body count (~5700)
    const float4* s4 = (const float4*)(s + head);
    float4*       d4 = (float4*)(d + head);

    // Register-blocked: 4 independent loads in flight, then 4 stores.
    for (int i0 = tid; i0 < nvec; i0 += 4 * NTHREADS) {
        int i1 = i0 + NTHREADS;
        int i2 = i0 + 2 * NTHREADS;
        int i3 = i0 + 3 * NTHREADS;
        float4 r0, r1, r2, r3;
        bool v1 = i1 < nvec, v2 = i2 < nvec, v3 = i3 < nvec;
        r0 = __ldcs(s4 + i0);
        if (v1) r1 = __ldcs(s4 + i1);
        if (v2) r2 = __ldcs(s4 + i2);
        if (v3) r3 = __ldcs(s4 + i3);
        __stcs(d4 + i0, r0);
        if (v1) __stcs(d4 + i1, r1);
        if (v2) __stcs(d4 + i2, r2);
        if (v3) __stcs(d4 + i3, r3);
    }

    int tail_start = head + (nvec << 2);
    int ntail = PLANE - tail_start;                 // 0..3 scalars
    if (tid < ntail) __stcs(d + tail_start + tid, __ldcs(s + tail_start + tid));

    // Prefetch this thread's slice of qus_type BEFORE the barrier — these are
    // input reads (no hazard), so their latency hides under the copy stores.
    int qtv[QT_PER_THREAD];
    #pragma unroll
    for (int k = 0; k < QT_PER_THREAD; k++)
        qtv[k] = __ldg(qus_type + tid + k * NTHREADS);

    __syncthreads();   // plane fully written before this CTA's atomics

    // --- Phase B: predicated scan + scatter-add into the hot plane ---
    int i  = p / (BOX - 1);
    int jj = p - i * (BOX - 1);
    int j  = jj + (jj >= i);

    #pragma unroll
    for (int k = 0; k < QT_PER_THREAD; k++) {
        if (qtv[k] == qt) {
            int b   = tid + k * NTHREADS;
            int ol1 = __ldg(obj_label + b * BOX + j);
            int ol2 = __ldg(obj_label + b * BOX + i);
            float a = __ldg(attention + b * BOX + i) * __ldg(attention + b * BOX + j);
            atomicAdd(d + ol1 * NUM_OT + ol2, a);
        }
    }
}

extern "C" void kernel_launch(void* const* d_in, const int* in_sizes, int n_in,
                              void* d_out, int out_size) {
    const int*   obj_label    = (const int*)d_in[0];
    const int*   qus_type     = (const int*)d_in[1];
    const float* attention    = (const float*)d_in[2];
    const float* score_matrix = (const float*)d_in[3];
    float*       out          = (float*)d_out;

    fused_plane_kernel<<<NPLANES, NTHREADS>>>(score_matrix, out,
                                              obj_label, qus_type, attention);
}